// round 10
// baseline (speedup 1.0000x reference)
#include <cuda_runtime.h>
#include <cstddef>

#define B 16
#define N 1024
#define P 256
#define D 64
#define K 26
#define S 4                 // n-segments (8192 streaming warps)
#define NSEG (N / S)        // 256 n per segment

#define PROD_CTAS 128       // importance producer CTAs (bids 0..127)
#define STREAM_CTAS (S * B * (P / 2) / 4)   // 2048 (128-thr CTAs, 4 warps)

// ---- scratch (no allocations allowed; device globals) ----
__device__ float g_importance[N];            // [n]
__device__ float g_pscore[S * B * P];        // [s, b*P+p] partial scores
__device__ float g_pmean[S * B * P * D];     // [s, b*P+p, d] partial sums
__device__ int   g_done;                     // producer-completion counter (reset by k_out)

// ------------------------------------------------------------------
// Kernel 1 (fused): importance producers + streaming pass.
//
// bid < 128  -> PRODUCER: importance[j] = mean_i adp[i,j] for 8 cols,
//               publish, bump g_done, exit. (~2.5us, wave-1 bids)
// bid >= 128 -> STREAMER: one HALF-WARP per (seg,b,p); 16 lanes x
//               float4 = d=64; adjacent p per warp -> contiguous 512B
//               per warp-iteration. Norms stashed in smem; the
//               score dot with importance happens AFTER the pass,
//               behind a spin on g_done (expected wait: zero).
// Deadlock-free: producers never wait; consumers spin only after
// ~170us of streaming, producers are first-dispatched.
// ------------------------------------------------------------------
__global__ void __launch_bounds__(128) k_main(const float* __restrict__ patches,
                                              const float* __restrict__ adp) {
    __shared__ float snorm[8][NSEG];    // per half-warp norms (8 KB)
    __shared__ float simp[NSEG];        // importance segment (1 KB)
    __shared__ float red[16][8];        // producer reduce

    int tid = threadIdx.x;
    int bid = blockIdx.x;

    if (bid < PROD_CTAS) {
        // ---------------- producer: 8 columns of adp ----------------
        int jl   = tid & 7;              // 0..7 col within CTA
        int iseg = tid >> 3;             // 0..15, 64 rows each
        int j    = bid * 8 + jl;

        float s = 0.f;
        const float* col = adp + (size_t)(iseg * 64) * N + j;
#pragma unroll 8
        for (int i = 0; i < 64; i++) s += col[(size_t)i * N];
        red[iseg][jl] = s;
        __syncthreads();
        if (tid < 8) {
            float t = 0.f;
#pragma unroll
            for (int r = 0; r < 16; r++) t += red[r][tid];
            g_importance[j - jl + tid] = t * (1.0f / (float)N);
            __threadfence();             // make column results device-visible
        }
        __syncthreads();
        if (tid == 0) {
            __threadfence();
            atomicAdd(&g_done, 1);       // release-publish
        }
        return;
    }

    // ---------------- streamer ----------------
    int sid   = bid - PROD_CTAS;                     // 0..2047
    int gwarp = (sid * 128 + tid) >> 5;              // 0 .. S*B*P/2-1
    int lane  = tid & 31;
    int half  = lane >> 4;
    int hl    = lane & 15;
    int hw    = tid >> 4;                            // 0..7 half-warp in CTA

    int seg   = gwarp / (B * (P / 2));               // CTA-uniform (512 CTAs/seg)
    int rem   = gwarp % (B * (P / 2));
    int b     = rem / (P / 2);
    int p     = (rem % (P / 2)) * 2 + half;
    int n0    = seg * NSEG;

    const float4* base =
        (const float4*)(patches + (((size_t)b * N + n0) * P + p) * (size_t)D) + hl;
    const size_t nstride = (size_t)P * D / 4;        // float4 per n

    float4 ms = make_float4(0.f, 0.f, 0.f, 0.f);

#pragma unroll 8
    for (int n = 0; n < NSEG; n++) {
        float4 v = __ldcs(base + (size_t)n * nstride);   // streaming, read-once
        ms.x += v.x; ms.y += v.y; ms.z += v.z; ms.w += v.w;
        float sq = v.x * v.x + v.y * v.y + v.z * v.z + v.w * v.w;
        sq += __shfl_xor_sync(0xffffffffu, sq, 8);
        sq += __shfl_xor_sync(0xffffffffu, sq, 4);
        sq += __shfl_xor_sync(0xffffffffu, sq, 2);
        sq += __shfl_xor_sync(0xffffffffu, sq, 1);
        if (hl == 0) snorm[hw][n] = sqrtf(sq);
    }

    // partial mean out (unchanged path)
    size_t bp = (size_t)b * P + p;
    ((float4*)g_pmean)[((size_t)seg * B * P + bp) * (D / 4) + hl] = ms;

    // wait for importance (producers finished long ago), load to smem
    if (tid == 0) {
        while (*(volatile int*)&g_done != PROD_CTAS) { }
        __threadfence();                 // acquire
    }
    __syncthreads();
    if (tid < 128) {
        simp[tid]       = g_importance[n0 + tid];
        simp[tid + 128] = g_importance[n0 + tid + 128];
    }
    __syncthreads();

    // score = sum_n norm[n] * imp[n]  (16-lane strided dot + butterfly)
    float acc = 0.f;
#pragma unroll
    for (int t = 0; t < 16; t++) {
        int n = hl + 16 * t;
        acc += snorm[hw][n] * simp[n];
    }
    acc += __shfl_xor_sync(0xffffffffu, acc, 8);
    acc += __shfl_xor_sync(0xffffffffu, acc, 4);
    acc += __shfl_xor_sync(0xffffffffu, acc, 2);
    acc += __shfl_xor_sync(0xffffffffu, acc, 1);
    if (hl == 0) g_pscore[(size_t)seg * B * P + bp] = acc;
}

// ------------------------------------------------------------------
// Kernel 2: fused score-reduce + top-k + anchor gather + replicate.
// Identical per-CTA reduction order -> identical rounding -> the 64
// CTAs of a batch agree on ranks. Matches jax.lax.top_k (descending,
// lower index wins ties). Also resets g_done for the next replay.
// ------------------------------------------------------------------
#define NN_PER_BLOCK 16
#define KD4 (K * D / 4)   // 416 float4 per anchor block

__global__ void __launch_bounds__(256) k_out(float* __restrict__ out) {
    const int chunks = N / NN_PER_BLOCK;          // 64
    int b = blockIdx.x / chunks;
    int c = blockIdx.x % chunks;
    int tid = threadIdx.x;

    if (blockIdx.x == 0 && tid == 0) g_done = 0;  // reset for next replay

    __shared__ float  sc[P];
    __shared__ int    tk[K];
    __shared__ float4 sa[KD4];

    {
        float my = 0.f;
#pragma unroll
        for (int s = 0; s < S; s++) my += g_pscore[s * B * P + b * P + tid];
        sc[tid] = my;
    }
    __syncthreads();

    {
        float my = sc[tid];
        int rank = 0;
#pragma unroll 8
        for (int q = 0; q < P; q++) {
            float v = sc[q];
            rank += (v > my) || (v == my && q < tid);
        }
        if (rank < K) tk[rank] = tid;
    }
    __syncthreads();

    const int MF4 = B * P * D / 4;                // float4 per segment
    const float inv = 1.0f / (float)N;
    for (int t = tid; t < KD4; t += blockDim.x) {
        int kk  = t >> 4;          // /(D/4)
        int dd4 = t & 15;
        size_t idx = ((size_t)b * P + tk[kk]) * (D / 4) + dd4;
        float4 acc = make_float4(0.f, 0.f, 0.f, 0.f);
#pragma unroll
        for (int s = 0; s < S; s++) {
            float4 v = ((const float4*)g_pmean)[(size_t)s * MF4 + idx];
            acc.x += v.x; acc.y += v.y; acc.z += v.z; acc.w += v.w;
        }
        sa[t] = make_float4(acc.x * inv, acc.y * inv, acc.z * inv, acc.w * inv);
    }
    __syncthreads();

    int t0 = tid;
    int t1 = tid + 256;
    float4 v0 = sa[t0];
    float4 v1 = (t1 < KD4) ? sa[t1] : make_float4(0, 0, 0, 0);

    float4* obase = (float4*)out + ((size_t)b * N + (size_t)c * NN_PER_BLOCK) * KD4;
#pragma unroll
    for (int nn = 0; nn < NN_PER_BLOCK; nn++) {
        float4* o = obase + (size_t)nn * KD4;
        __stcs(o + t0, v0);
        if (t1 < KD4) __stcs(o + t1, v1);
    }
}

// ------------------------------------------------------------------
extern "C" void kernel_launch(void* const* d_in, const int* in_sizes, int n_in,
                              void* d_out, int out_size) {
    const float* patches = (const float*)d_in[0];
    const float* adp     = (const float*)d_in[1];
    if (n_in >= 2 && in_sizes[0] == N * N && in_sizes[1] == B * N * P * D) {
        const float* t = patches; patches = adp; adp = t;
    }
    float* out = (float*)d_out;

    k_main<<<PROD_CTAS + STREAM_CTAS, 128>>>(patches, adp);  // 2176 CTAs
    k_out<<<B * (N / NN_PER_BLOCK), 256>>>(out);
}

// round 11
// speedup vs baseline: 1.0026x; 1.0026x over previous
#include <cuda_runtime.h>
#include <cstddef>

#define B 16
#define N 1024
#define P 256
#define D 64
#define K 26
#define S 4                 // n-segments (8192 streaming warps)
#define NSEG (N / S)        // 256 n per segment

#define PROD_CTAS 128       // importance producer CTAs (bids 0..127)
#define STREAM_CTAS (S * B * (P / 2) / 4)   // 2048 (128-thr CTAs, 4 warps)
#define CTAS_PER_BATCH (STREAM_CTAS / B)    // 128

#define KD4 (K * D / 4)     // 416 float4 per anchor block

// ---- scratch (no allocations allowed; device globals) ----
__device__ float g_importance[N];            // [n]
__device__ float g_pscore[S * B * P];        // [s, b*P+p] partial scores
__device__ float g_pmean[S * B * P * D];     // [s, b*P+p, d] partial sums
__device__ float g_anchor[B * K * D];        // [b, k, d] finalized anchors
__device__ int   g_done;                     // importance-producer counter
__device__ int   g_cnt[B];                   // per-batch streamer-done counters

// ------------------------------------------------------------------
// Kernel 1 (fused): importance producers + streaming pass + per-batch
// finalizers.
//
// bid < 128  -> PRODUCER: importance[j] = mean_i adp[i,j] for 8 cols,
//               publish, bump g_done, exit. (~2.5us, wave-1 bids)
// bid >= 128 -> STREAMER: one HALF-WARP per (seg,b,p); 16 lanes x
//               float4 = d=64; adjacent p per warp -> contiguous 512B
//               per warp-iteration. Norms stashed in smem; the score
//               dot with importance happens AFTER the pass behind a
//               spin on g_done (expected wait: zero).
//               The LAST streamer CTA of each batch (atomic counter)
//               finalizes: score reduce (fixed order -> deterministic)
//               -> stable top-k (jax.lax.top_k semantics: descending,
//               lower index wins ties) -> anchor reduce -> g_anchor.
// Deadlock-free: producers never wait; consumer spin happens after
// ~170us of streaming; finalizer runs only when its batch is done.
// ------------------------------------------------------------------
__global__ void __launch_bounds__(128) k_main(const float* __restrict__ patches,
                                              const float* __restrict__ adp) {
    __shared__ float snorm[8][NSEG];    // per half-warp norms (8 KB)
    __shared__ float simp[NSEG];        // importance segment (1 KB)
    __shared__ float red[16][8];        // producer reduce
    __shared__ float sc[P];             // finalizer: reduced scores
    __shared__ int   tk[K];             // finalizer: top-k indices
    __shared__ int   s_islast;

    int tid = threadIdx.x;
    int bid = blockIdx.x;

    if (bid < PROD_CTAS) {
        // ---------------- producer: 8 columns of adp ----------------
        int jl   = tid & 7;              // 0..7 col within CTA
        int iseg = tid >> 3;             // 0..15, 64 rows each
        int j    = bid * 8 + jl;

        float s = 0.f;
        const float* col = adp + (size_t)(iseg * 64) * N + j;
#pragma unroll 8
        for (int i = 0; i < 64; i++) s += col[(size_t)i * N];
        red[iseg][jl] = s;
        __syncthreads();
        if (tid < 8) {
            float t = 0.f;
#pragma unroll
            for (int r = 0; r < 16; r++) t += red[r][tid];
            g_importance[j - jl + tid] = t * (1.0f / (float)N);
        }
        __threadfence();
        __syncthreads();
        if (tid == 0) atomicAdd(&g_done, 1);   // release-publish
        return;
    }

    // ---------------- streamer ----------------
    int sid   = bid - PROD_CTAS;                     // 0..2047
    int gwarp = (sid * 128 + tid) >> 5;              // 0 .. S*B*P/2-1
    int lane  = tid & 31;
    int half  = lane >> 4;
    int hl    = lane & 15;
    int hw    = tid >> 4;                            // 0..7 half-warp in CTA

    int seg   = gwarp / (B * (P / 2));               // CTA-uniform
    int rem   = gwarp % (B * (P / 2));
    int b     = rem / (P / 2);                       // CTA-uniform
    int p     = (rem % (P / 2)) * 2 + half;
    int n0    = seg * NSEG;

    const float4* base =
        (const float4*)(patches + (((size_t)b * N + n0) * P + p) * (size_t)D) + hl;
    const size_t nstride = (size_t)P * D / 4;        // float4 per n

    float4 ms = make_float4(0.f, 0.f, 0.f, 0.f);

#pragma unroll 8
    for (int n = 0; n < NSEG; n++) {
        float4 v = __ldcs(base + (size_t)n * nstride);   // streaming, read-once
        ms.x += v.x; ms.y += v.y; ms.z += v.z; ms.w += v.w;
        float sq = v.x * v.x + v.y * v.y + v.z * v.z + v.w * v.w;
        sq += __shfl_xor_sync(0xffffffffu, sq, 8);
        sq += __shfl_xor_sync(0xffffffffu, sq, 4);
        sq += __shfl_xor_sync(0xffffffffu, sq, 2);
        sq += __shfl_xor_sync(0xffffffffu, sq, 1);
        if (hl == 0) snorm[hw][n] = sqrtf(sq);
    }

    // partial mean out
    size_t bp = (size_t)b * P + p;
    ((float4*)g_pmean)[((size_t)seg * B * P + bp) * (D / 4) + hl] = ms;

    // wait for importance (producers finished ~165us ago), load to smem
    if (tid == 0) {
        while (*(volatile int*)&g_done != PROD_CTAS) { }
    }
    __syncthreads();
    __threadfence();                     // acquire
    if (tid < 128) {
        simp[tid]       = g_importance[n0 + tid];
        simp[tid + 128] = g_importance[n0 + tid + 128];
    }
    __syncthreads();

    // score = sum_n norm[n] * imp[n]  (16-lane strided dot + butterfly)
    float acc = 0.f;
#pragma unroll
    for (int t = 0; t < 16; t++) {
        int n = hl + 16 * t;
        acc += snorm[hw][n] * simp[n];
    }
    acc += __shfl_xor_sync(0xffffffffu, acc, 8);
    acc += __shfl_xor_sync(0xffffffffu, acc, 4);
    acc += __shfl_xor_sync(0xffffffffu, acc, 2);
    acc += __shfl_xor_sync(0xffffffffu, acc, 1);
    if (hl == 0) g_pscore[(size_t)seg * B * P + bp] = acc;

    // ---------------- per-batch finalizer election ----------------
    __threadfence();                     // publish pscore/pmean
    __syncthreads();
    if (tid == 0) {
        int old = atomicAdd(&g_cnt[b], 1);
        s_islast = (old == CTAS_PER_BATCH - 1);
    }
    __syncthreads();
    if (!s_islast) return;
    __threadfence();                     // acquire all batch-b partials

    // 1. reduce partial scores (fixed order -> deterministic)
    for (int pp = tid; pp < P; pp += 128) {
        float v = 0.f;
#pragma unroll
        for (int s = 0; s < S; s++) v += g_pscore[s * B * P + b * P + pp];
        sc[pp] = v;
    }
    __syncthreads();

    // 2. stable rank-count top-k
    for (int pp = tid; pp < P; pp += 128) {
        float my = sc[pp];
        int rank = 0;
#pragma unroll 8
        for (int q = 0; q < P; q++) {
            float v = sc[q];
            rank += (v > my) || (v == my && q < pp);
        }
        if (rank < K) tk[rank] = pp;
    }
    __syncthreads();

    // 3. reduce + scale the 26x64 anchor block
    const int MF4 = B * P * D / 4;
    const float inv = 1.0f / (float)N;
    for (int t = tid; t < KD4; t += 128) {
        int kk  = t >> 4;
        int dd4 = t & 15;
        size_t idx = ((size_t)b * P + tk[kk]) * (D / 4) + dd4;
        float4 a = make_float4(0.f, 0.f, 0.f, 0.f);
#pragma unroll
        for (int s = 0; s < S; s++) {
            float4 v = ((const float4*)g_pmean)[(size_t)s * MF4 + idx];
            a.x += v.x; a.y += v.y; a.z += v.z; a.w += v.w;
        }
        ((float4*)g_anchor)[(size_t)b * KD4 + t] =
            make_float4(a.x * inv, a.y * inv, a.z * inv, a.w * inv);
    }
}

// ------------------------------------------------------------------
// Kernel 2: pure replicator. Each thread holds <=2 float4 of batch b's
// anchor block (L2-hot, 6.6KB) and streams 16 n-replicas. Also resets
// the coordination counters for the next graph replay.
// ------------------------------------------------------------------
#define NN_PER_BLOCK 16

__global__ void __launch_bounds__(256) k_out(float* __restrict__ out) {
    const int chunks = N / NN_PER_BLOCK;          // 64
    int b = blockIdx.x / chunks;
    int c = blockIdx.x % chunks;
    int tid = threadIdx.x;

    if (blockIdx.x == 0) {                        // reset for next replay
        if (tid == 0) g_done = 0;
        if (tid < B)  g_cnt[tid] = 0;
    }

    int t0 = tid;
    int t1 = tid + 256;
    float4 v0 = ((const float4*)g_anchor)[(size_t)b * KD4 + t0];
    float4 v1 = (t1 < KD4) ? ((const float4*)g_anchor)[(size_t)b * KD4 + t1]
                           : make_float4(0, 0, 0, 0);

    float4* obase = (float4*)out + ((size_t)b * N + (size_t)c * NN_PER_BLOCK) * KD4;
#pragma unroll
    for (int nn = 0; nn < NN_PER_BLOCK; nn++) {
        float4* o = obase + (size_t)nn * KD4;
        __stcs(o + t0, v0);
        if (t1 < KD4) __stcs(o + t1, v1);
    }
}

// ------------------------------------------------------------------
extern "C" void kernel_launch(void* const* d_in, const int* in_sizes, int n_in,
                              void* d_out, int out_size) {
    const float* patches = (const float*)d_in[0];
    const float* adp     = (const float*)d_in[1];
    if (n_in >= 2 && in_sizes[0] == N * N && in_sizes[1] == B * N * P * D) {
        const float* t = patches; patches = adp; adp = t;
    }
    float* out = (float*)d_out;

    k_main<<<PROD_CTAS + STREAM_CTAS, 128>>>(patches, adp);  // 2176 CTAs
    k_out<<<B * (N / NN_PER_BLOCK), 256>>>(out);
}